// round 16
// baseline (speedup 1.0000x reference)
#include <cuda_runtime.h>
#include <cuda_bf16.h>
#include <math.h>

// ---------------------------------------------------------------------------
// Problem constants
// ---------------------------------------------------------------------------
#define TSEQ 2048
#define HD   512
#define EMB  512
#define G4H  2048
#define NTAGS 12
#define START_TAG 10
#define STOP_TAG  11
#define NEGV (-10000.0f)
#define NINF (-3e38f)

#define NCH 128      // viterbi chunks
#define CL  16       // steps per chunk

// ---------------------------------------------------------------------------
// Scratch — R14 LAYOUT EXACTLY (order and sizes). DO NOT REORDER: the 32 hot
// stamp lines' L2 placement is part of the measured-best configuration.
// New counters are APPENDED at the end only.
// ---------------------------------------------------------------------------
__device__ float g_x0[TSEQ * EMB];
__device__ float g_G[2 * TSEQ * G4H];
__device__ float g_hcat0[TSEQ * 2 * HD];
__device__ float g_hcat1[TSEQ * 2 * HD];
__device__ float g_feats[TSEQ * NTAGS];
__device__ unsigned long long g_hstamp[2 * 2 * HD]; // [dir][par][H]
__device__ int g_ticket;
__device__ int g_ready[2][32];                      // [dir][mtile] layer0 G
// viterbi scratch (appended AFTER all R11 globals)
__device__ float g_M[NCH][NTAGS][NTAGS];
__device__ float g_fvc[NCH][NTAGS];
__device__ unsigned char g_pm[NCH][NTAGS][CL];
__device__ float g_score;
__device__ int g_blast;
// NEW (appended): layer1 G readiness + hcat0 row-group completion
__device__ int g_ready1[2][32];                     // [dir][mtile] layer1 G
__device__ int g_grp[2][32];                        // [dir][group] hcat0 done

// ---------------------------------------------------------------------------
// Helpers
// ---------------------------------------------------------------------------
__device__ __forceinline__ unsigned long long ld_relaxed_u64(const unsigned long long* p) {
    unsigned long long v;
    asm volatile("ld.relaxed.gpu.global.b64 %0, [%1];" : "=l"(v) : "l"(p) : "memory");
    return v;
}
__device__ __forceinline__ void st_relaxed_u64(unsigned long long* p, unsigned long long v) {
    asm volatile("st.relaxed.gpu.global.b64 [%0], %1;" :: "l"(p), "l"(v) : "memory");
}
__device__ __forceinline__ int ld_acquire_s32(const int* p) {
    int v;
    asm volatile("ld.acquire.gpu.global.s32 %0, [%1];" : "=r"(v) : "l"(p) : "memory");
    return v;
}
__device__ __forceinline__ unsigned long long ffma2(unsigned long long a,
                                                    unsigned long long b,
                                                    unsigned long long c) {
    unsigned long long d;
    asm("fma.rn.f32x2 %0, %1, %2, %3;" : "=l"(d) : "l"(a), "l"(b), "l"(c));
    return d;
}
__device__ __forceinline__ float2 unpack2(unsigned long long v) {
    float2 r;
    asm("mov.b64 {%0, %1}, %2;" : "=f"(r.x), "=f"(r.y) : "l"(v));
    return r;
}
__device__ __forceinline__ float tanh_hw(float x) {
    float y;
    asm("tanh.approx.f32 %0, %1;" : "=f"(y) : "f"(x));
    return y;
}
__device__ __forceinline__ float sig_hw(float x) {
    return fmaf(0.5f, tanh_hw(0.5f * x), 0.5f);
}
__device__ __forceinline__ unsigned f2tf(float x) {
    unsigned r;
    asm("cvt.rna.tf32.f32 %0, %1;" : "=r"(r) : "f"(x));
    return r;
}
__device__ __forceinline__ void mma_tf32(float* c, const unsigned* a,
                                         unsigned b0, unsigned b1) {
    asm("mma.sync.aligned.m16n8k8.row.col.f32.tf32.tf32.f32 "
        "{%0,%1,%2,%3}, {%4,%5,%6,%7}, {%8,%9}, {%0,%1,%2,%3};"
        : "+f"(c[0]), "+f"(c[1]), "+f"(c[2]), "+f"(c[3])
        : "r"(a[0]), "r"(a[1]), "r"(a[2]), "r"(a[3]), "r"(b0), "r"(b1));
}
__device__ __forceinline__ void bar_sync(int id, int cnt) {
    asm volatile("bar.sync %0, %1;" :: "r"(id), "r"(cnt) : "memory");
}
__device__ __forceinline__ void bar_arrive(int id, int cnt) {
    asm volatile("bar.arrive %0, %1;" :: "r"(id), "r"(cnt) : "memory");
}

// ---------------------------------------------------------------------------
// 0) single init: stamps + ticket + all counters (once per replay)
// ---------------------------------------------------------------------------
__global__ void init_stamps_kernel() {
    int i = blockIdx.x * blockDim.x + threadIdx.x;
    if (i < 2 * 2 * HD) g_hstamp[i] = 0ULL;
    if (i == 0) g_ticket = 0;
    if (i < 64) ((int*)g_ready)[i] = 0;
    if (i < 64) ((int*)g_ready1)[i] = 0;
    if (i < 64) ((int*)g_grp)[i] = 0;
}

// ---------------------------------------------------------------------------
// 1) embedding gather
// ---------------------------------------------------------------------------
__global__ void embed_kernel(const int* __restrict__ sentence,
                             const float* __restrict__ emb) {
    int t = blockIdx.x;
    int v = sentence[t];
    const float4* src = (const float4*)(emb + (size_t)v * EMB);
    float4* dst = (float4*)(g_x0 + (size_t)t * EMB);
    dst[threadIdx.x] = src[threadIdx.x];
}

// ---------------------------------------------------------------------------
// 2) SINGLE-LAUNCH fused kernel: both layers' scans + both layers' GEMMs.
//    GEMM tickets 0..1023 = layer0 (ungated); 1024..2047 = layer1, gated on
//    hcat0 group completion (g_grp, published by layer0 cell warps).
//    Scan: layer loop; stamps monotonic (layer1 need = 2048+s) — no reset.
// ---------------------------------------------------------------------------
#define FUSED_THREADS 416
#define SCAN_CNT 288
#define GEMM_CNT 128
#define NTILES_TOTAL 2048

__global__ void __launch_bounds__(FUSED_THREADS, 1)
scan_gemm_kernel(const float* __restrict__ Whh0,
                 const float* __restrict__ Wih0,
                 const float* __restrict__ b10,
                 const float* __restrict__ b20,
                 const float* __restrict__ Whh1,
                 const float* __restrict__ Wih1,
                 const float* __restrict__ b11,
                 const float* __restrict__ b21) {
    __shared__ unsigned Ah[16][72], Al[16][72];
    __shared__ unsigned Bh[16][136], Bl[16][136];
    __shared__ __align__(16) float hbuf[8][64];
    __shared__ float part[2][8][32];
    __shared__ int s_ticket;

    const int dir = blockIdx.x >> 6;
    const int cta = blockIdx.x & 63;
    const int j0  = cta * 8;
    const int tid = threadIdx.x;
    const int w   = tid >> 5;
    const int lane = tid & 31;

    unsigned long long* stampBase = g_hstamp + (size_t)dir * 2 * HD;
    const float* Gd = g_G + (size_t)dir * TSEQ * G4H;

    if (w < 4) {
        // ================= GEMM warps (both layers) =================
        const int g = lane >> 2, tig = lane & 3;
        const int lr = tid >> 1;
        const int lc = (tid & 1) * 8;

        for (;;) {
            if (tid == 0) s_ticket = atomicAdd(&g_ticket, 1);
            bar_sync(3, GEMM_CNT);
            int tk = s_ticket;
            if (tk >= NTILES_TOTAL) break;

            const int layer = tk >> 10;
            const int tl = tk & 1023;
            int gg = tl >> 5;
            int r = tl & 31;
            int tdir = r >> 4;
            int ntile = r & 15;
            int mtile = tdir ? (31 - gg) : gg;

            const int K = layer ? (2 * HD) : EMB;
            const float* Asrc = layer ? g_hcat0 : g_x0;
            const float* WihL = layer ? Wih1 : Wih0;
            const float* b1L  = layer ? b11 : b10;
            const float* b2L  = layer ? b21 : b20;

            // layer1 tiles: wait for hcat0 rows [64m,64m+64) — fwd group m
            // and bwd group 31-m complete (also implies g_G overwrite safety)
            if (layer) {
                if (tid == 0) {
                    while (ld_acquire_s32(&g_grp[0][mtile]) < 64) {}
                    while (ld_acquire_s32(&g_grp[1][31 - mtile]) < 64) {}
                }
                bar_sync(3, GEMM_CNT);
            }

            const float* Wd = WihL + (size_t)tdir * G4H * K;
            const float* b1d = b1L + (size_t)tdir * G4H;
            const float* b2d = b2L + (size_t)tdir * G4H;
            float* Cd = g_G + (size_t)tdir * TSEQ * G4H;

            float acc[16][4];
#pragma unroll
            for (int nt = 0; nt < 16; nt++)
#pragma unroll
                for (int q = 0; q < 4; q++) acc[nt][q] = 0.0f;

            const float* Arow = Asrc + (size_t)(mtile * 64 + lr) * K + lc;
            const float* Wrow = Wd + (size_t)(ntile * 128 + tid) * K;

            for (int k0 = 0; k0 < K; k0 += 16) {
                float av[8], wv[16];
                *(float4*)(av)      = *(const float4*)(Arow + k0);
                *(float4*)(av + 4)  = *(const float4*)(Arow + k0 + 4);
                *(float4*)(wv)      = *(const float4*)(Wrow + k0);
                *(float4*)(wv + 4)  = *(const float4*)(Wrow + k0 + 4);
                *(float4*)(wv + 8)  = *(const float4*)(Wrow + k0 + 8);
                *(float4*)(wv + 12) = *(const float4*)(Wrow + k0 + 12);
                bar_sync(3, GEMM_CNT);
#pragma unroll
                for (int i = 0; i < 8; i++) {
                    unsigned hi = f2tf(av[i]);
                    Ah[lc + i][lr] = hi;
                    Al[lc + i][lr] = f2tf(av[i] - __uint_as_float(hi));
                }
#pragma unroll
                for (int j = 0; j < 16; j++) {
                    unsigned wh = f2tf(wv[j]);
                    Bh[j][tid] = wh;
                    Bl[j][tid] = f2tf(wv[j] - __uint_as_float(wh));
                }
                bar_sync(3, GEMM_CNT);

#pragma unroll
                for (int ks = 0; ks < 16; ks += 8) {
                    unsigned ah[4], al[4];
                    int r0 = w * 16 + g;
                    ah[0] = Ah[ks + tig][r0];
                    ah[1] = Ah[ks + tig][r0 + 8];
                    ah[2] = Ah[ks + tig + 4][r0];
                    ah[3] = Ah[ks + tig + 4][r0 + 8];
                    al[0] = Al[ks + tig][r0];
                    al[1] = Al[ks + tig][r0 + 8];
                    al[2] = Al[ks + tig + 4][r0];
                    al[3] = Al[ks + tig + 4][r0 + 8];
#pragma unroll
                    for (int nt = 0; nt < 16; nt++) {
                        int n = nt * 8 + g;
                        unsigned bh0 = Bh[ks + tig][n];
                        unsigned bh1 = Bh[ks + tig + 4][n];
                        unsigned bl0 = Bl[ks + tig][n];
                        unsigned bl1 = Bl[ks + tig + 4][n];
                        mma_tf32(acc[nt], ah, bh0, bh1);
                        mma_tf32(acc[nt], ah, bl0, bl1);
                        mma_tf32(acc[nt], al, bh0, bh1);
                    }
                }
            }

            int row = mtile * 64 + w * 16 + g;
#pragma unroll
            for (int nt = 0; nt < 16; nt++) {
                int n = ntile * 128 + nt * 8 + 2 * tig;
                float bias0 = b1d[n] + b2d[n];
                float bias1 = b1d[n + 1] + b2d[n + 1];
                float2 v0, v1;
                v0.x = acc[nt][0] + bias0; v0.y = acc[nt][1] + bias1;
                v1.x = acc[nt][2] + bias0; v1.y = acc[nt][3] + bias1;
                *(float2*)(Cd + (size_t)row * G4H + n)       = v0;
                *(float2*)(Cd + (size_t)(row + 8) * G4H + n) = v1;
            }
            __threadfence();
            bar_sync(3, GEMM_CNT);
            if (tid == 0) {
                if (layer) atomicAdd(&g_ready1[tdir][mtile], 1);
                else       atomicAdd(&g_ready[tdir][mtile], 1);
            }
        }
        return;
    }

    if (w == 12) {
        // ================= cell warp (layer loop) =================
        for (int layer = 0; layer < 2; layer++) {
            float* hcat = layer ? g_hcat1 : g_hcat0;
            const unsigned base = (unsigned)layer * TSEQ;   // stamp offset
            float creg = 0.0f;
            for (int s = 0; s < TSEQ; s++) {
                const int t   = dir ? (TSEQ - 1 - s) : s;
                const int par = s & 1;
                bar_sync(1 + par, SCAN_CNT);

                float g = part[par][0][lane];
#pragma unroll
                for (int p = 1; p < 8; p++) g += part[par][p][lane];

                float act = ((lane & 24) == 16) ? tanh_hw(g) : sig_hw(g);
                float af = __shfl_down_sync(0xffffffffu, act, 8);
                float tg = __shfl_down_sync(0xffffffffu, act, 16);
                float ao = __shfl_down_sync(0xffffffffu, act, 24);
                if (lane < 8) {
                    float c = af * creg + act * tg;
                    creg = c;
                    float h = ao * tanh_hw(c);
                    unsigned long long pk =
                        ((unsigned long long)(base + (unsigned)(s + 1)) << 32) |
                        (unsigned long long)__float_as_uint(h);
                    st_relaxed_u64(stampBase + (size_t)par * HD + j0 + lane, pk);
                    hcat[(size_t)t * (2 * HD) + dir * HD + j0 + lane] = h;
                }
                // layer0: publish hcat0 group completion every 64 steps
                if (layer == 0 && (s & 63) == 63) {
                    __syncwarp();
                    if (lane == 0) {
                        __threadfence();
                        atomicAdd(&g_grp[dir][s >> 6], 1);
                    }
                }
            }
        }
    } else {
        // ================= producer warps (layer loop) =================
        const int seg = w - 4;
        const int row = lane;
        const int q = row >> 3, jj = row & 7;
        const int R = q * HD + j0 + jj;

        for (int layer = 0; layer < 2; layer++) {
            const float* WhhL = layer ? Whh1 : Whh0;
            const unsigned base = (unsigned)layer * TSEQ;
            const int* rdy = layer ? g_ready1[dir] : g_ready[dir];

            const ulonglong2* wsrc2 =
                (const ulonglong2*)(WhhL + ((size_t)dir * G4H + R) * HD + seg * 64);
            ulonglong2 w2[16];
#pragma unroll
            for (int i = 0; i < 16; i++) w2[i] = wsrc2[i];

            float gnext = 0.0f;
            int lastGrp = -1;
            if (seg == 7) {
                int t0 = dir ? (TSEQ - 1) : 0;
                int grp = t0 >> 6;
                while (ld_acquire_s32(&rdy[grp]) < 16) {}
                lastGrp = grp;
                gnext = __ldg(Gd + (size_t)t0 * G4H + R);
            }

            for (int s = 0; s < TSEQ; s++) {
                const int par = s & 1;

                if (s == 0) {
                    hbuf[seg][lane * 2]     = 0.0f;
                    hbuf[seg][lane * 2 + 1] = 0.0f;
                } else {
                    const unsigned long long* src =
                        stampBase + ((size_t)((s + 1) & 1)) * HD + seg * 64 + lane * 2;
                    const unsigned need = base + (unsigned)s;
                    unsigned long long v0, v1;
                    for (;;) {
                        v0 = ld_relaxed_u64(src);
                        v1 = ld_relaxed_u64(src + 1);
                        bool ok = ((unsigned)(v0 >> 32) >= need) &&
                                  ((unsigned)(v1 >> 32) >= need);
                        if (__all_sync(0xffffffffu, ok)) break;
                    }
                    hbuf[seg][lane * 2]     = __uint_as_float((unsigned)v0);
                    hbuf[seg][lane * 2 + 1] = __uint_as_float((unsigned)v1);
                }
                __syncwarp();

                const ulonglong2* hb2 = (const ulonglong2*)hbuf[seg];
                unsigned long long a0 = 0ULL, a1 = 0ULL, a2 = 0ULL, a3 = 0ULL;
#pragma unroll
                for (int i = 0; i < 16; i += 2) {
                    ulonglong2 h0 = hb2[i];
                    ulonglong2 h1 = hb2[i + 1];
                    a0 = ffma2(w2[i].x,     h0.x, a0);
                    a1 = ffma2(w2[i].y,     h0.y, a1);
                    a2 = ffma2(w2[i + 1].x, h1.x, a2);
                    a3 = ffma2(w2[i + 1].y, h1.y, a3);
                }
                float2 f0 = unpack2(a0), f1 = unpack2(a1),
                       f2 = unpack2(a2), f3 = unpack2(a3);
                float pr =
                    ((f0.x + f0.y) + (f1.x + f1.y)) + ((f2.x + f2.y) + (f3.x + f3.y));

                if (seg == 7) {
                    pr += gnext;
                    part[par][7][row] = pr;
                    if (s + 1 < TSEQ) {
                        int tn = dir ? (TSEQ - 2 - s) : (s + 1);
                        int grp = tn >> 6;
                        if (grp != lastGrp) {
                            while (ld_acquire_s32(&rdy[grp]) < 16) {}
                            lastGrp = grp;
                        }
                        gnext = __ldg(Gd + (size_t)tn * G4H + R);
                    }
                } else {
                    part[par][seg][row] = pr;
                }

                bar_arrive(1 + par, SCAN_CNT);
            }
        }
    }
}

// ---------------------------------------------------------------------------
// 4) tag projection
// ---------------------------------------------------------------------------
__global__ void feats_kernel(const float* __restrict__ Wtag,
                             const float* __restrict__ btag) {
    int t = blockIdx.x;
    __shared__ float xs[2 * HD];
    for (int i = threadIdx.x; i < 2 * HD; i += 192)
        xs[i] = g_hcat1[(size_t)t * (2 * HD) + i];
    __syncthreads();
    int tag = threadIdx.x / 16;
    int sg  = threadIdx.x % 16;
    const float* w = Wtag + (size_t)tag * (2 * HD) + sg * 64;
    const float* x = xs + sg * 64;
    float s = 0.0f;
#pragma unroll
    for (int i = 0; i < 64; i++) s = fmaf(w[i], x[i], s);
#pragma unroll
    for (int o = 8; o > 0; o >>= 1)
        s += __shfl_down_sync(0xffffffffu, s, o, 16);
    if (sg == 0) g_feats[t * NTAGS + tag] = s + btag[tag];
}

// ---------------------------------------------------------------------------
// 5) Chunked Viterbi (validated)
// ---------------------------------------------------------------------------
__global__ void vit_basis_kernel(const float* __restrict__ trans) {
    int c = blockIdx.x;
    int j = threadIdx.x;
    __shared__ float tr[NTAGS][NTAGS];
    __shared__ float ft[CL][NTAGS];
    for (int i = threadIdx.x; i < NTAGS * NTAGS; i += 32)
        tr[i / NTAGS][i % NTAGS] = trans[i];
    for (int i = threadIdx.x; i < CL * NTAGS; i += 32)
        ft[i / NTAGS][i % NTAGS] = g_feats[c * CL * NTAGS + i];
    __syncwarp();

    if (j < NTAGS) {
        float v[NTAGS];
#pragma unroll
        for (int p = 0; p < NTAGS; p++) v[p] = (p == j) ? 0.0f : NINF;
        for (int k = 0; k < CL; k++) {
            float nv[NTAGS];
#pragma unroll
            for (int i = 0; i < NTAGS; i++) {
                float b = NINF;
#pragma unroll
                for (int p = 0; p < NTAGS; p++) b = fmaxf(b, v[p] + tr[i][p]);
                nv[i] = b + ft[k][i];
            }
#pragma unroll
            for (int i = 0; i < NTAGS; i++) v[i] = nv[i];
        }
#pragma unroll
        for (int i = 0; i < NTAGS; i++) g_M[c][i][j] = v[i];
    }
}

__global__ void vit_scan_kernel(const float* __restrict__ trans) {
    extern __shared__ float sM[];
    for (int i = threadIdx.x; i < NCH * NTAGS * NTAGS; i += blockDim.x)
        sM[i] = ((const float*)g_M)[i];
    __syncthreads();
    if (threadIdx.x >= 32) return;
    int lane = threadIdx.x;

    float fv = (lane == START_TAG) ? 0.0f : ((lane < NTAGS) ? NEGV : NINF);
    for (int c = 0; c < NCH; c++) {
        if (lane < NTAGS) g_fvc[c][lane] = fv;
        float b = NINF;
#pragma unroll
        for (int jj = 0; jj < NTAGS; jj++) {
            float fj = __shfl_sync(0xffffffffu, fv, jj);
            if (lane < NTAGS)
                b = fmaxf(b, fj + sM[c * 144 + lane * NTAGS + jj]);
        }
        fv = (lane < NTAGS) ? b : NINF;
    }
    float term = (lane < NTAGS) ? fv + trans[STOP_TAG * NTAGS + lane] : NINF;
    float bs = term;
    int bi = lane;
#pragma unroll
    for (int o = 16; o > 0; o >>= 1) {
        float os = __shfl_down_sync(0xffffffffu, bs, o);
        int   oi = __shfl_down_sync(0xffffffffu, bi, o);
        if (os > bs || (os == bs && oi < bi)) { bs = os; bi = oi; }
    }
    if (lane == 0) { g_score = bs; g_blast = bi; }
}

__global__ void vit_chunk_kernel(const float* __restrict__ trans) {
    int c = blockIdx.x;
    int lane = threadIdx.x;
    __shared__ float tr[NTAGS][NTAGS];
    __shared__ float ft[CL][NTAGS];
    __shared__ unsigned char bp[CL][NTAGS];
    for (int i = lane; i < NTAGS * NTAGS; i += 32)
        tr[i / NTAGS][i % NTAGS] = trans[i];
    for (int i = lane; i < CL * NTAGS; i += 32)
        ft[i / NTAGS][i % NTAGS] = g_feats[c * CL * NTAGS + i];
    __syncwarp();

    float fv = (lane < NTAGS) ? g_fvc[c][lane] : NINF;
    for (int k = 0; k < CL; k++) {
        float b = NINF;
        int arg = 0;
#pragma unroll
        for (int p = 0; p < NTAGS; p++) {
            float fp = __shfl_sync(0xffffffffu, fv, p);
            if (lane < NTAGS) {
                float sc = fp + tr[lane][p];
                if (sc > b) { b = sc; arg = p; }
            }
        }
        if (lane < NTAGS) {
            bp[k][lane] = (unsigned char)arg;
            fv = b + ft[k][lane];
        } else {
            fv = NINF;
        }
    }
    __syncwarp();
    if (lane < NTAGS) {
        int tag = lane;
        for (int k = CL - 1; k >= 0; k--) {
            tag = bp[k][tag];
            g_pm[c][lane][k] = (unsigned char)tag;
        }
    }
}

__global__ void vit_out_kernel(float* __restrict__ out, int out_size) {
    __shared__ unsigned char spm[NCH][NTAGS][CL];
    for (int i = threadIdx.x; i < NCH * NTAGS * CL; i += blockDim.x)
        ((unsigned char*)spm)[i] = ((const unsigned char*)g_pm)[i];
    __syncthreads();
    if (threadIdx.x != 0) return;

    float score = g_score;
    int tag = g_blast;
    if (out_size >= TSEQ + 1) {
        out[0] = score;
        out[TSEQ] = (float)tag;
        for (int c = NCH - 1; c >= 0; c--) {
            for (int k = CL - 1; k >= 0; k--) {
                int t = c * CL + k;
                int s = spm[c][tag][k];
                if (t >= 1) out[t] = (float)s;
            }
            tag = spm[c][tag][0];
        }
        for (int i = TSEQ + 1; i < out_size; i++) out[i] = 0.0f;
    } else {
        for (int c = NCH - 1; c >= 0; c--) {
            for (int k = CL - 1; k >= 0; k--) {
                int t = c * CL + k;
                int s = spm[c][tag][k];
                if (t >= 1 && t < out_size) out[t] = (float)s;
            }
            tag = spm[c][tag][0];
        }
        if (out_size > 0) out[0] = score;
    }
}

// ---------------------------------------------------------------------------
// launch — single fused scan+gemm launch for both layers
// ---------------------------------------------------------------------------
extern "C" void kernel_launch(void* const* d_in, const int* in_sizes, int n_in,
                              void* d_out, int out_size) {
    const int*   sentence = (const int*)  d_in[0];
    const float* emb      = (const float*)d_in[1];
    const float* Wih0     = (const float*)d_in[2];
    const float* Whh0     = (const float*)d_in[3];
    const float* bih0     = (const float*)d_in[4];
    const float* bhh0     = (const float*)d_in[5];
    const float* Wih1     = (const float*)d_in[6];
    const float* Whh1     = (const float*)d_in[7];
    const float* bih1     = (const float*)d_in[8];
    const float* bhh1     = (const float*)d_in[9];
    const float* Wtag     = (const float*)d_in[10];
    const float* btag     = (const float*)d_in[11];
    const float* trans    = (const float*)d_in[12];
    float* out = (float*)d_out;

    cudaFuncSetAttribute(vit_scan_kernel,
                         cudaFuncAttributeMaxDynamicSharedMemorySize,
                         NCH * NTAGS * NTAGS * (int)sizeof(float));

    init_stamps_kernel<<<4, 512>>>();
    embed_kernel<<<TSEQ, 128>>>(sentence, emb);

    scan_gemm_kernel<<<128, FUSED_THREADS>>>(Whh0, Wih0, bih0, bhh0,
                                             Whh1, Wih1, bih1, bhh1);

    feats_kernel<<<TSEQ, 192>>>(Wtag, btag);
    vit_basis_kernel<<<NCH, 32>>>(trans);
    vit_scan_kernel<<<1, 256, NCH * NTAGS * NTAGS * sizeof(float)>>>(trans);
    vit_chunk_kernel<<<NCH, 32>>>(trans);
    vit_out_kernel<<<1, 256>>>(out, out_size);
}

// round 17
// speedup vs baseline: 1.0414x; 1.0414x over previous
#include <cuda_runtime.h>
#include <cuda_bf16.h>
#include <math.h>

// ---------------------------------------------------------------------------
// Problem constants
// ---------------------------------------------------------------------------
#define TSEQ 2048
#define HD   512
#define EMB  512
#define G4H  2048
#define NTAGS 12
#define START_TAG 10
#define STOP_TAG  11
#define NEGV (-10000.0f)
#define NINF (-3e38f)

#define NCH 128      // viterbi chunks
#define CL  16       // steps per chunk

// ---------------------------------------------------------------------------
// Scratch — R15 LAYOUT EXACTLY (order and sizes). DO NOT REORDER: the 32 hot
// stamp lines' L2 placement is part of the measured-best configuration.
// ---------------------------------------------------------------------------
__device__ float g_x0[TSEQ * EMB];
__device__ float g_G[2 * TSEQ * G4H];
__device__ float g_hcat0[TSEQ * 2 * HD];
__device__ float g_hcat1[TSEQ * 2 * HD];
__device__ float g_feats[TSEQ * NTAGS];
__device__ unsigned long long g_hstamp[2 * 2 * HD]; // [dir][par][H]
__device__ int g_ticket;
__device__ int g_ready[2][32];                      // [dir][mtile]
// viterbi scratch (appended AFTER all R11 globals)
__device__ float g_M[NCH][NTAGS][NTAGS];
__device__ float g_fvc[NCH][NTAGS];
__device__ unsigned char g_pm[NCH][NTAGS][CL];
__device__ float g_score;
__device__ int g_blast;

// ---------------------------------------------------------------------------
// Helpers
// ---------------------------------------------------------------------------
__device__ __forceinline__ unsigned long long ld_relaxed_u64(const unsigned long long* p) {
    unsigned long long v;
    asm volatile("ld.relaxed.gpu.global.b64 %0, [%1];" : "=l"(v) : "l"(p) : "memory");
    return v;
}
__device__ __forceinline__ void st_relaxed_u64(unsigned long long* p, unsigned long long v) {
    asm volatile("st.relaxed.gpu.global.b64 [%0], %1;" :: "l"(p), "l"(v) : "memory");
}
__device__ __forceinline__ int ld_acquire_s32(const int* p) {
    int v;
    asm volatile("ld.acquire.gpu.global.s32 %0, [%1];" : "=r"(v) : "l"(p) : "memory");
    return v;
}
__device__ __forceinline__ unsigned long long ffma2(unsigned long long a,
                                                    unsigned long long b,
                                                    unsigned long long c) {
    unsigned long long d;
    asm("fma.rn.f32x2 %0, %1, %2, %3;" : "=l"(d) : "l"(a), "l"(b), "l"(c));
    return d;
}
__device__ __forceinline__ float2 unpack2(unsigned long long v) {
    float2 r;
    asm("mov.b64 {%0, %1}, %2;" : "=f"(r.x), "=f"(r.y) : "l"(v));
    return r;
}
__device__ __forceinline__ float tanh_hw(float x) {
    float y;
    asm("tanh.approx.f32 %0, %1;" : "=f"(y) : "f"(x));
    return y;
}
__device__ __forceinline__ float sig_hw(float x) {
    return fmaf(0.5f, tanh_hw(0.5f * x), 0.5f);
}
__device__ __forceinline__ unsigned f2tf(float x) {
    unsigned r;
    asm("cvt.rna.tf32.f32 %0, %1;" : "=r"(r) : "f"(x));
    return r;
}
__device__ __forceinline__ void mma_tf32(float* c, const unsigned* a,
                                         unsigned b0, unsigned b1) {
    asm("mma.sync.aligned.m16n8k8.row.col.f32.tf32.tf32.f32 "
        "{%0,%1,%2,%3}, {%4,%5,%6,%7}, {%8,%9}, {%0,%1,%2,%3};"
        : "+f"(c[0]), "+f"(c[1]), "+f"(c[2]), "+f"(c[3])
        : "r"(a[0]), "r"(a[1]), "r"(a[2]), "r"(a[3]), "r"(b0), "r"(b1));
}
__device__ __forceinline__ void bar_sync(int id, int cnt) {
    asm volatile("bar.sync %0, %1;" :: "r"(id), "r"(cnt) : "memory");
}
__device__ __forceinline__ void bar_arrive(int id, int cnt) {
    asm volatile("bar.arrive %0, %1;" :: "r"(id), "r"(cnt) : "memory");
}

// ---------------------------------------------------------------------------
// 0) reset stamps + ticket + ready (before each fused launch)
// ---------------------------------------------------------------------------
__global__ void init_stamps_kernel() {
    int i = blockIdx.x * blockDim.x + threadIdx.x;
    if (i < 2 * 2 * HD) g_hstamp[i] = 0ULL;
    if (i == 0) g_ticket = 0;
    if (i < 64) ((int*)g_ready)[i] = 0;
}

// ---------------------------------------------------------------------------
// 1) embedding gather
// ---------------------------------------------------------------------------
__global__ void embed_kernel(const int* __restrict__ sentence,
                             const float* __restrict__ emb) {
    int t = blockIdx.x;
    int v = sentence[t];
    const float4* src = (const float4*)(emb + (size_t)v * EMB);
    float4* dst = (float4*)(g_x0 + (size_t)t * EMB);
    dst[threadIdx.x] = src[threadIdx.x];
}

// ---------------------------------------------------------------------------
// 2) FUSED scan + background GEMM — R15 VERBATIM (best measured: 3868us)
// ---------------------------------------------------------------------------
#define FUSED_THREADS 416
#define SCAN_CNT 288
#define GEMM_CNT 128
#define NTILES_TOTAL 1024

__global__ void __launch_bounds__(FUSED_THREADS, 1)
scan_gemm_kernel(const float* __restrict__ Whh,
                 const float* __restrict__ Wih,
                 const float* __restrict__ b1,
                 const float* __restrict__ b2,
                 int layer) {
    __shared__ unsigned Ah[16][72], Al[16][72];
    __shared__ unsigned Bh[16][136], Bl[16][136];
    __shared__ __align__(16) float hbuf[8][64];
    __shared__ float part[2][8][32];
    __shared__ int s_ticket;

    const int K = layer ? (2 * HD) : EMB;
    const float* Asrc = layer ? g_hcat0 : g_x0;
    float* hcat = layer ? g_hcat1 : g_hcat0;

    const int dir = blockIdx.x >> 6;
    const int cta = blockIdx.x & 63;
    const int j0  = cta * 8;
    const int tid = threadIdx.x;
    const int w   = tid >> 5;
    const int lane = tid & 31;

    unsigned long long* stampBase = g_hstamp + (size_t)dir * 2 * HD;
    const float* Gd = g_G + (size_t)dir * TSEQ * G4H;

    if (w < 4) {
        // ================= GEMM warps =================
        const int g = lane >> 2, tig = lane & 3;
        const int lr = tid >> 1;
        const int lc = (tid & 1) * 8;

        for (;;) {
            if (tid == 0) s_ticket = atomicAdd(&g_ticket, 1);
            bar_sync(3, GEMM_CNT);
            int tk = s_ticket;
            if (tk >= NTILES_TOTAL) break;

            int gg = tk >> 5;
            int r = tk & 31;
            int tdir = r >> 4;
            int ntile = r & 15;
            int mtile = tdir ? (31 - gg) : gg;

            const float* Wd = Wih + (size_t)tdir * G4H * K;
            const float* b1d = b1 + (size_t)tdir * G4H;
            const float* b2d = b2 + (size_t)tdir * G4H;
            float* Cd = g_G + (size_t)tdir * TSEQ * G4H;

            float acc[16][4];
#pragma unroll
            for (int nt = 0; nt < 16; nt++)
#pragma unroll
                for (int q = 0; q < 4; q++) acc[nt][q] = 0.0f;

            const float* Arow = Asrc + (size_t)(mtile * 64 + lr) * K + lc;
            const float* Wrow = Wd + (size_t)(ntile * 128 + tid) * K;

            for (int k0 = 0; k0 < K; k0 += 16) {
                float av[8], wv[16];
                *(float4*)(av)      = *(const float4*)(Arow + k0);
                *(float4*)(av + 4)  = *(const float4*)(Arow + k0 + 4);
                *(float4*)(wv)      = *(const float4*)(Wrow + k0);
                *(float4*)(wv + 4)  = *(const float4*)(Wrow + k0 + 4);
                *(float4*)(wv + 8)  = *(const float4*)(Wrow + k0 + 8);
                *(float4*)(wv + 12) = *(const float4*)(Wrow + k0 + 12);
                bar_sync(3, GEMM_CNT);
#pragma unroll
                for (int i = 0; i < 8; i++) {
                    unsigned hi = f2tf(av[i]);
                    Ah[lc + i][lr] = hi;
                    Al[lc + i][lr] = f2tf(av[i] - __uint_as_float(hi));
                }
#pragma unroll
                for (int j = 0; j < 16; j++) {
                    unsigned wh = f2tf(wv[j]);
                    Bh[j][tid] = wh;
                    Bl[j][tid] = f2tf(wv[j] - __uint_as_float(wh));
                }
                bar_sync(3, GEMM_CNT);

#pragma unroll
                for (int ks = 0; ks < 16; ks += 8) {
                    unsigned ah[4], al[4];
                    int r0 = w * 16 + g;
                    ah[0] = Ah[ks + tig][r0];
                    ah[1] = Ah[ks + tig][r0 + 8];
                    ah[2] = Ah[ks + tig + 4][r0];
                    ah[3] = Ah[ks + tig + 4][r0 + 8];
                    al[0] = Al[ks + tig][r0];
                    al[1] = Al[ks + tig][r0 + 8];
                    al[2] = Al[ks + tig + 4][r0];
                    al[3] = Al[ks + tig + 4][r0 + 8];
#pragma unroll
                    for (int nt = 0; nt < 16; nt++) {
                        int n = nt * 8 + g;
                        unsigned bh0 = Bh[ks + tig][n];
                        unsigned bh1 = Bh[ks + tig + 4][n];
                        unsigned bl0 = Bl[ks + tig][n];
                        unsigned bl1 = Bl[ks + tig + 4][n];
                        mma_tf32(acc[nt], ah, bh0, bh1);
                        mma_tf32(acc[nt], ah, bl0, bl1);
                        mma_tf32(acc[nt], al, bh0, bh1);
                    }
                }
            }

            int row = mtile * 64 + w * 16 + g;
#pragma unroll
            for (int nt = 0; nt < 16; nt++) {
                int n = ntile * 128 + nt * 8 + 2 * tig;
                float bias0 = b1d[n] + b2d[n];
                float bias1 = b1d[n + 1] + b2d[n + 1];
                float2 v0, v1;
                v0.x = acc[nt][0] + bias0; v0.y = acc[nt][1] + bias1;
                v1.x = acc[nt][2] + bias0; v1.y = acc[nt][3] + bias1;
                *(float2*)(Cd + (size_t)row * G4H + n)       = v0;
                *(float2*)(Cd + (size_t)(row + 8) * G4H + n) = v1;
            }
            __threadfence();
            bar_sync(3, GEMM_CNT);
            if (tid == 0) atomicAdd(&g_ready[tdir][mtile], 1);
        }
        return;
    }

    if (w == 12) {
        // ================= cell warp (shortened tail) =================
        float creg = 0.0f;
        for (int s = 0; s < TSEQ; s++) {
            const int t   = dir ? (TSEQ - 1 - s) : s;
            const int par = s & 1;
            bar_sync(1 + par, SCAN_CNT);

            float g = part[par][0][lane];
#pragma unroll
            for (int p = 1; p < 8; p++) g += part[par][p][lane];

            float act = ((lane & 24) == 16) ? tanh_hw(g) : sig_hw(g);
            float af = __shfl_down_sync(0xffffffffu, act, 8);
            float tg = __shfl_down_sync(0xffffffffu, act, 16);
            float ao = __shfl_down_sync(0xffffffffu, act, 24);
            if (lane < 8) {
                float c = af * creg + act * tg;
                creg = c;
                float h = ao * tanh_hw(c);
                unsigned long long pk =
                    ((unsigned long long)(unsigned)(s + 1) << 32) |
                    (unsigned long long)__float_as_uint(h);
                st_relaxed_u64(stampBase + (size_t)par * HD + j0 + lane, pk);
                hcat[(size_t)t * (2 * HD) + dir * HD + j0 + lane] = h;
            }
        }
    } else {
        // ================= producer warps =================
        const int seg = w - 4;
        const int row = lane;
        const int q = row >> 3, jj = row & 7;
        const int R = q * HD + j0 + jj;

        const ulonglong2* wsrc2 =
            (const ulonglong2*)(Whh + ((size_t)dir * G4H + R) * HD + seg * 64);
        ulonglong2 w2[16];
#pragma unroll
        for (int i = 0; i < 16; i++) w2[i] = wsrc2[i];

        float gnext = 0.0f;
        int lastGrp = -1;
        if (seg == 7) {
            int t0 = dir ? (TSEQ - 1) : 0;
            int grp = t0 >> 6;
            while (ld_acquire_s32(&g_ready[dir][grp]) < 16) {}
            lastGrp = grp;
            gnext = __ldg(Gd + (size_t)t0 * G4H + R);
        }

        for (int s = 0; s < TSEQ; s++) {
            const int par = s & 1;

            if (s == 0) {
                hbuf[seg][lane * 2]     = 0.0f;
                hbuf[seg][lane * 2 + 1] = 0.0f;
            } else {
                const unsigned long long* src =
                    stampBase + ((size_t)((s + 1) & 1)) * HD + seg * 64 + lane * 2;
                const unsigned need = (unsigned)s;
                unsigned long long v0, v1;
                for (;;) {
                    v0 = ld_relaxed_u64(src);
                    v1 = ld_relaxed_u64(src + 1);
                    bool ok = ((unsigned)(v0 >> 32) >= need) &&
                              ((unsigned)(v1 >> 32) >= need);
                    if (__all_sync(0xffffffffu, ok)) break;
                }
                hbuf[seg][lane * 2]     = __uint_as_float((unsigned)v0);
                hbuf[seg][lane * 2 + 1] = __uint_as_float((unsigned)v1);
            }
            __syncwarp();

            const ulonglong2* hb2 = (const ulonglong2*)hbuf[seg];
            unsigned long long a0 = 0ULL, a1 = 0ULL, a2 = 0ULL, a3 = 0ULL;
#pragma unroll
            for (int i = 0; i < 16; i += 2) {
                ulonglong2 h0 = hb2[i];
                ulonglong2 h1 = hb2[i + 1];
                a0 = ffma2(w2[i].x,     h0.x, a0);
                a1 = ffma2(w2[i].y,     h0.y, a1);
                a2 = ffma2(w2[i + 1].x, h1.x, a2);
                a3 = ffma2(w2[i + 1].y, h1.y, a3);
            }
            float2 f0 = unpack2(a0), f1 = unpack2(a1),
                   f2 = unpack2(a2), f3 = unpack2(a3);
            float pr =
                ((f0.x + f0.y) + (f1.x + f1.y)) + ((f2.x + f2.y) + (f3.x + f3.y));

            if (seg == 7) {
                pr += gnext;
                part[par][7][row] = pr;
                if (s + 1 < TSEQ) {
                    int tn = dir ? (TSEQ - 2 - s) : (s + 1);
                    int grp = tn >> 6;
                    if (grp != lastGrp) {
                        while (ld_acquire_s32(&g_ready[dir][grp]) < 16) {}
                        lastGrp = grp;
                    }
                    gnext = __ldg(Gd + (size_t)tn * G4H + R);
                }
            } else {
                part[par][seg][row] = pr;
            }

            bar_arrive(1 + par, SCAN_CNT);
        }
    }
}

// ---------------------------------------------------------------------------
// 4) tag projection — REWRITTEN: 128 blocks stage W_tag once in smem;
//    each of 8 warps handles 2 timesteps (hcat row in registers, 12
//    conflict-free smem dots, shfl reduce). Was 111us (per-t W_tag restream).
// ---------------------------------------------------------------------------
__global__ void __launch_bounds__(256)
feats_kernel(const float* __restrict__ Wtag,
             const float* __restrict__ btag) {
    __shared__ float wsh[NTAGS * 2 * HD];   // 48 KB
    __shared__ float bsh[NTAGS];
    for (int i = threadIdx.x; i < NTAGS * 2 * HD; i += 256)
        wsh[i] = Wtag[i];
    if (threadIdx.x < NTAGS) bsh[threadIdx.x] = btag[threadIdx.x];
    __syncthreads();

    const int warp = threadIdx.x >> 5;
    const int lane = threadIdx.x & 31;

#pragma unroll
    for (int tt = 0; tt < 2; tt++) {
        int t = blockIdx.x * 16 + warp * 2 + tt;
        // hcat1[t] row into registers: 8 x float4 per lane (k = c*128 + lane*4)
        const float4* xp = (const float4*)(g_hcat1 + (size_t)t * (2 * HD));
        float4 xv[8];
#pragma unroll
        for (int c = 0; c < 8; c++) xv[c] = xp[c * 32 + lane];

#pragma unroll
        for (int tag = 0; tag < NTAGS; tag++) {
            const float4* wp = (const float4*)(wsh + tag * (2 * HD));
            float s = 0.0f;
#pragma unroll
            for (int c = 0; c < 8; c++) {
                float4 wv = wp[c * 32 + lane];
                s = fmaf(xv[c].x, wv.x, s);
                s = fmaf(xv[c].y, wv.y, s);
                s = fmaf(xv[c].z, wv.z, s);
                s = fmaf(xv[c].w, wv.w, s);
            }
#pragma unroll
            for (int o = 16; o > 0; o >>= 1)
                s += __shfl_down_sync(0xffffffffu, s, o);
            if (lane == 0) g_feats[t * NTAGS + tag] = s + bsh[tag];
        }
    }
}

// ---------------------------------------------------------------------------
// 5) Chunked Viterbi (validated)
// ---------------------------------------------------------------------------
__global__ void vit_basis_kernel(const float* __restrict__ trans) {
    int c = blockIdx.x;
    int j = threadIdx.x;
    __shared__ float tr[NTAGS][NTAGS];
    __shared__ float ft[CL][NTAGS];
    for (int i = threadIdx.x; i < NTAGS * NTAGS; i += 32)
        tr[i / NTAGS][i % NTAGS] = trans[i];
    for (int i = threadIdx.x; i < CL * NTAGS; i += 32)
        ft[i / NTAGS][i % NTAGS] = g_feats[c * CL * NTAGS + i];
    __syncwarp();

    if (j < NTAGS) {
        float v[NTAGS];
#pragma unroll
        for (int p = 0; p < NTAGS; p++) v[p] = (p == j) ? 0.0f : NINF;
        for (int k = 0; k < CL; k++) {
            float nv[NTAGS];
#pragma unroll
            for (int i = 0; i < NTAGS; i++) {
                float b = NINF;
#pragma unroll
                for (int p = 0; p < NTAGS; p++) b = fmaxf(b, v[p] + tr[i][p]);
                nv[i] = b + ft[k][i];
            }
#pragma unroll
            for (int i = 0; i < NTAGS; i++) v[i] = nv[i];
        }
#pragma unroll
        for (int i = 0; i < NTAGS; i++) g_M[c][i][j] = v[i];
    }
}

__global__ void vit_scan_kernel(const float* __restrict__ trans) {
    extern __shared__ float sM[];
    for (int i = threadIdx.x; i < NCH * NTAGS * NTAGS; i += blockDim.x)
        sM[i] = ((const float*)g_M)[i];
    __syncthreads();
    if (threadIdx.x >= 32) return;
    int lane = threadIdx.x;

    float fv = (lane == START_TAG) ? 0.0f : ((lane < NTAGS) ? NEGV : NINF);
    for (int c = 0; c < NCH; c++) {
        if (lane < NTAGS) g_fvc[c][lane] = fv;
        float b = NINF;
#pragma unroll
        for (int jj = 0; jj < NTAGS; jj++) {
            float fj = __shfl_sync(0xffffffffu, fv, jj);
            if (lane < NTAGS)
                b = fmaxf(b, fj + sM[c * 144 + lane * NTAGS + jj]);
        }
        fv = (lane < NTAGS) ? b : NINF;
    }
    float term = (lane < NTAGS) ? fv + trans[STOP_TAG * NTAGS + lane] : NINF;
    float bs = term;
    int bi = lane;
#pragma unroll
    for (int o = 16; o > 0; o >>= 1) {
        float os = __shfl_down_sync(0xffffffffu, bs, o);
        int   oi = __shfl_down_sync(0xffffffffu, bi, o);
        if (os > bs || (os == bs && oi < bi)) { bs = os; bi = oi; }
    }
    if (lane == 0) { g_score = bs; g_blast = bi; }
}

__global__ void vit_chunk_kernel(const float* __restrict__ trans) {
    int c = blockIdx.x;
    int lane = threadIdx.x;
    __shared__ float tr[NTAGS][NTAGS];
    __shared__ float ft[CL][NTAGS];
    __shared__ unsigned char bp[CL][NTAGS];
    for (int i = lane; i < NTAGS * NTAGS; i += 32)
        tr[i / NTAGS][i % NTAGS] = trans[i];
    for (int i = lane; i < CL * NTAGS; i += 32)
        ft[i / NTAGS][i % NTAGS] = g_feats[c * CL * NTAGS + i];
    __syncwarp();

    float fv = (lane < NTAGS) ? g_fvc[c][lane] : NINF;
    for (int k = 0; k < CL; k++) {
        float b = NINF;
        int arg = 0;
#pragma unroll
        for (int p = 0; p < NTAGS; p++) {
            float fp = __shfl_sync(0xffffffffu, fv, p);
            if (lane < NTAGS) {
                float sc = fp + tr[lane][p];
                if (sc > b) { b = sc; arg = p; }
            }
        }
        if (lane < NTAGS) {
            bp[k][lane] = (unsigned char)arg;
            fv = b + ft[k][lane];
        } else {
            fv = NINF;
        }
    }
    __syncwarp();
    if (lane < NTAGS) {
        int tag = lane;
        for (int k = CL - 1; k >= 0; k--) {
            tag = bp[k][tag];
            g_pm[c][lane][k] = (unsigned char)tag;
        }
    }
}

__global__ void vit_out_kernel(float* __restrict__ out, int out_size) {
    __shared__ unsigned char spm[NCH][NTAGS][CL];
    for (int i = threadIdx.x; i < NCH * NTAGS * CL; i += blockDim.x)
        ((unsigned char*)spm)[i] = ((const unsigned char*)g_pm)[i];
    __syncthreads();
    if (threadIdx.x != 0) return;

    float score = g_score;
    int tag = g_blast;
    if (out_size >= TSEQ + 1) {
        out[0] = score;
        out[TSEQ] = (float)tag;
        for (int c = NCH - 1; c >= 0; c--) {
            for (int k = CL - 1; k >= 0; k--) {
                int t = c * CL + k;
                int s = spm[c][tag][k];
                if (t >= 1) out[t] = (float)s;
            }
            tag = spm[c][tag][0];
        }
        for (int i = TSEQ + 1; i < out_size; i++) out[i] = 0.0f;
    } else {
        for (int c = NCH - 1; c >= 0; c--) {
            for (int k = CL - 1; k >= 0; k--) {
                int t = c * CL + k;
                int s = spm[c][tag][k];
                if (t >= 1 && t < out_size) out[t] = (float)s;
            }
            tag = spm[c][tag][0];
        }
        if (out_size > 0) out[0] = score;
    }
}

// ---------------------------------------------------------------------------
// launch — R15 sequencing with fast feats
// ---------------------------------------------------------------------------
extern "C" void kernel_launch(void* const* d_in, const int* in_sizes, int n_in,
                              void* d_out, int out_size) {
    const int*   sentence = (const int*)  d_in[0];
    const float* emb      = (const float*)d_in[1];
    const float* Wih0     = (const float*)d_in[2];
    const float* Whh0     = (const float*)d_in[3];
    const float* bih0     = (const float*)d_in[4];
    const float* bhh0     = (const float*)d_in[5];
    const float* Wih1     = (const float*)d_in[6];
    const float* Whh1     = (const float*)d_in[7];
    const float* bih1     = (const float*)d_in[8];
    const float* bhh1     = (const float*)d_in[9];
    const float* Wtag     = (const float*)d_in[10];
    const float* btag     = (const float*)d_in[11];
    const float* trans    = (const float*)d_in[12];
    float* out = (float*)d_out;

    cudaFuncSetAttribute(vit_scan_kernel,
                         cudaFuncAttributeMaxDynamicSharedMemorySize,
                         NCH * NTAGS * NTAGS * (int)sizeof(float));

    embed_kernel<<<TSEQ, 128>>>(sentence, emb);

    // ---- layer 0 (fused GEMM + scan) ----
    init_stamps_kernel<<<4, 512>>>();
    scan_gemm_kernel<<<128, FUSED_THREADS>>>(Whh0, Wih0, bih0, bhh0, 0);

    // ---- layer 1 (fused GEMM + scan) ----
    init_stamps_kernel<<<4, 512>>>();
    scan_gemm_kernel<<<128, FUSED_THREADS>>>(Whh1, Wih1, bih1, bhh1, 1);

    // ---- CRF ----
    feats_kernel<<<128, 256>>>(Wtag, btag);
    vit_basis_kernel<<<NCH, 32>>>(trans);
    vit_scan_kernel<<<1, 256, NCH * NTAGS * NTAGS * sizeof(float)>>>(trans);
    vit_chunk_kernel<<<NCH, 32>>>(trans);
    vit_out_kernel<<<1, 256>>>(out, out_size);
}